// round 7
// baseline (speedup 1.0000x reference)
#include <cuda_runtime.h>
#include <cuda_bf16.h>
#include <cstdint>

#define N_NODES 100000
#define F_IN    500
#define HID     256
#define C_OUT   40
#define ALPHA0  0.1f
#define K_PAD   512
#define BK      32
#define NCHUNK  16
#define BM      128
#define N2      48

// ---------------------------------------------------------------------------
// Device-global scratch (allocation-free rule)
// ---------------------------------------------------------------------------
__device__ float g_h2[(size_t)N_NODES * C_OUT];                       // 16 MB
__device__ __align__(16) __nv_bfloat16 g_w1t_hi[HID * K_PAD];
__device__ __align__(16) __nv_bfloat16 g_w1t_lo[HID * K_PAD];
__device__ __align__(16) __nv_bfloat16 g_w2t_hi[N2 * HID];
__device__ __align__(16) __nv_bfloat16 g_w2t_lo[N2 * HID];

// ---------------------------------------------------------------------------
// Helpers
// ---------------------------------------------------------------------------
__device__ __forceinline__ uint32_t smem_u32(const void* p) {
    uint32_t a;
    asm("{ .reg .u64 t; cvta.to.shared.u64 t, %1; cvt.u32.u64 %0, t; }" : "=r"(a) : "l"(p));
    return a;
}

__device__ __forceinline__ uint32_t pack_bf2(float lo, float hi) {
    uint32_t r;
    asm("cvt.rn.bf16x2.f32 %0, %1, %2;" : "=r"(r) : "f"(hi), "f"(lo));
    return r;
}
__device__ __forceinline__ float bf_lo(uint32_t w) { return __uint_as_float(w << 16); }
__device__ __forceinline__ float bf_hi(uint32_t w) { return __uint_as_float(w & 0xffff0000u); }

__device__ __forceinline__ void mma_bf16(float d[4], const uint32_t a[4], const uint32_t b[2]) {
    asm volatile("mma.sync.aligned.m16n8k16.row.col.f32.bf16.bf16.f32 "
                 "{%0,%1,%2,%3},{%4,%5,%6,%7},{%8,%9},{%0,%1,%2,%3};"
                 : "+f"(d[0]), "+f"(d[1]), "+f"(d[2]), "+f"(d[3])
                 : "r"(a[0]), "r"(a[1]), "r"(a[2]), "r"(a[3]), "r"(b[0]), "r"(b[1]));
}

#define CP_ASYNC16(dst, src) \
    asm volatile("cp.async.cg.shared.global [%0], [%1], 16;" :: "r"(dst), "l"(src))
#define CP_COMMIT() asm volatile("cp.async.commit_group;" ::: "memory")
#define CP_WAIT0()  asm volatile("cp.async.wait_group 0;" ::: "memory")

// ---------------------------------------------------------------------------
// Dynamic SMEM layout (bytes)
// ---------------------------------------------------------------------------
#define APAD 40
#define SA_HI(b) ((b) * 61440)
#define SA_LO(b) ((b) * 61440 + 10240)
#define SB_HI(b) ((b) * 61440 + 20480)
#define SB_LO(b) ((b) * 61440 + 40960)
#define HPAD 264
#define SH_HI 0
#define SH_LO 67584
#define SW_HI 135168
#define SW_LO 160512
#define DSMEM_BYTES 185856

// ---------------------------------------------------------------------------
// Prep: bf16 hi/lo images of W1^T (bias folded at k=500) and W2^T (pad 40->48)
// ---------------------------------------------------------------------------
__global__ void prep_kernel(const float* __restrict__ W1,
                            const float* __restrict__ b1,
                            const float* __restrict__ W2)
{
    const int idx = blockIdx.x * blockDim.x + threadIdx.x;
    if (idx < HID * K_PAD) {
        const int n = idx >> 9;
        const int k = idx & (K_PAD - 1);
        float v = 0.f;
        if (k < F_IN)       v = W1[(size_t)k * HID + n];
        else if (k == F_IN) v = b1[n];
        const __nv_bfloat16 h = __float2bfloat16_rn(v);
        g_w1t_hi[idx] = h;
        g_w1t_lo[idx] = __float2bfloat16_rn(v - __bfloat162float(h));
    } else {
        const int i = idx - HID * K_PAD;
        if (i < N2 * HID) {
            const int n = i >> 8;
            const int k = i & 255;
            const float v = (n < C_OUT) ? W2[(size_t)k * C_OUT + n] : 0.f;
            const __nv_bfloat16 h = __float2bfloat16_rn(v);
            g_w2t_hi[i] = h;
            g_w2t_lo[i] = __float2bfloat16_rn(v - __bfloat162float(h));
        }
    }
}

// ---------------------------------------------------------------------------
// Fused GEMM1(+bias+ReLU)+GEMM2(+bias), mma.sync bf16 split (3 terms).
// 512 threads / 16 warps; GEMM1 warp tile 32x64; GEMM2 split over all 16 warps.
// ---------------------------------------------------------------------------
__global__ void __launch_bounds__(512, 1) fused_kernel(
    const float* __restrict__ x,
    const float* __restrict__ b2,
    float* __restrict__ out)
{
    extern __shared__ char dsm[];
    __shared__ float s_b2[C_OUT];
    const uint32_t smbase = smem_u32(dsm);
    const int tid  = threadIdx.x;
    const int lane = tid & 31, wid = tid >> 5;
    const int grp  = lane >> 2, tid4 = lane & 3;
    const int wm   = wid >> 2, wn = wid & 3;      // GEMM1: wm,wn in 0..3
    const int blockRow = blockIdx.x * BM;

    if (tid < C_OUT) s_b2[tid] = b2[tid];

    // A global-load mapping: 128 rows x 4 threads, 8 floats each
    const int ar  = tid >> 2;
    const int akq = (tid & 3) * 8;

    // B cp.async mapping: 256 rows x 2 threads, 16B each
    const int brow = tid >> 1;
    const int bseg = tid & 1;

    float acc[2][8][4];
    #pragma unroll
    for (int i = 0; i < 2; i++)
        #pragma unroll
        for (int j = 0; j < 8; j++)
            #pragma unroll
            for (int q = 0; q < 4; q++)
                acc[i][j][q] = 0.f;

    const int grow = blockRow + ar;
    const bool rok = grow < N_NODES;
    const float* xrow = x + (size_t)grow * F_IN;

    float4 av[2];

    auto loadA = [&](int c) {
        const int gk0 = c * BK + akq;
        #pragma unroll
        for (int h = 0; h < 2; h++) {
            const int gk = gk0 + h * 4;
            float4 v = make_float4(0.f, 0.f, 0.f, 0.f);
            if (rok) {
                if (gk + 3 < F_IN) {
                    v = *(const float4*)(xrow + gk);
                } else {
                    v.x = (gk + 0 < F_IN) ? xrow[gk + 0] : (gk + 0 == F_IN ? 1.f : 0.f);
                    v.y = (gk + 1 < F_IN) ? xrow[gk + 1] : (gk + 1 == F_IN ? 1.f : 0.f);
                    v.z = (gk + 2 < F_IN) ? xrow[gk + 2] : (gk + 2 == F_IN ? 1.f : 0.f);
                    v.w = (gk + 3 < F_IN) ? xrow[gk + 3] : (gk + 3 == F_IN ? 1.f : 0.f);
                }
            }
            av[h] = v;
        }
    };
    auto stsA = [&](int buf) {
        #pragma unroll
        for (int h = 0; h < 2; h++) {
            const int o = ar * APAD + akq + h * 4;
            const uint32_t h0 = pack_bf2(av[h].x, av[h].y);
            const uint32_t h1 = pack_bf2(av[h].z, av[h].w);
            const uint32_t l0 = pack_bf2(av[h].x - bf_lo(h0), av[h].y - bf_hi(h0));
            const uint32_t l1 = pack_bf2(av[h].z - bf_lo(h1), av[h].w - bf_hi(h1));
            *(uint2*)(dsm + SA_HI(buf) + o * 2) = make_uint2(h0, h1);
            *(uint2*)(dsm + SA_LO(buf) + o * 2) = make_uint2(l0, l1);
        }
    };
    auto cpB = [&](int c, int buf) {
        const uint32_t dhi = smbase + SB_HI(buf) + brow * (APAD * 2) + bseg * 16;
        const uint32_t dlo = smbase + SB_LO(buf) + brow * (APAD * 2) + bseg * 16;
        const __nv_bfloat16* shi = g_w1t_hi + (size_t)brow * K_PAD + c * BK + bseg * 8;
        const __nv_bfloat16* slo = g_w1t_lo + (size_t)brow * K_PAD + c * BK + bseg * 8;
        CP_ASYNC16(dhi, shi);
        CP_ASYNC16(dhi + 32, shi + 16);
        CP_ASYNC16(dlo, slo);
        CP_ASYNC16(dlo + 32, slo + 16);
    };
    auto mmaChunk = [&](int buf) {
        #pragma unroll
        for (int s = 0; s < 2; s++) {
            const int kk = s * 16 + tid4 * 2;
            uint32_t Ah[2][4], Al[2][4];
            #pragma unroll
            for (int i = 0; i < 2; i++) {
                const int o1 = (wm * 32 + i * 16 + grp) * APAD + kk;
                const int o2 = o1 + 8 * APAD;
                Ah[i][0] = *(const uint32_t*)(dsm + SA_HI(buf) + o1 * 2);
                Ah[i][1] = *(const uint32_t*)(dsm + SA_HI(buf) + o2 * 2);
                Ah[i][2] = *(const uint32_t*)(dsm + SA_HI(buf) + (o1 + 8) * 2);
                Ah[i][3] = *(const uint32_t*)(dsm + SA_HI(buf) + (o2 + 8) * 2);
                Al[i][0] = *(const uint32_t*)(dsm + SA_LO(buf) + o1 * 2);
                Al[i][1] = *(const uint32_t*)(dsm + SA_LO(buf) + o2 * 2);
                Al[i][2] = *(const uint32_t*)(dsm + SA_LO(buf) + (o1 + 8) * 2);
                Al[i][3] = *(const uint32_t*)(dsm + SA_LO(buf) + (o2 + 8) * 2);
            }
            #pragma unroll
            for (int j = 0; j < 8; j++) {
                const int o = (wn * 64 + j * 8 + grp) * APAD + kk;
                uint32_t Bh[2], Bl[2];
                Bh[0] = *(const uint32_t*)(dsm + SB_HI(buf) + o * 2);
                Bh[1] = *(const uint32_t*)(dsm + SB_HI(buf) + (o + 8) * 2);
                Bl[0] = *(const uint32_t*)(dsm + SB_LO(buf) + o * 2);
                Bl[1] = *(const uint32_t*)(dsm + SB_LO(buf) + (o + 8) * 2);
                #pragma unroll
                for (int i = 0; i < 2; i++) {
                    mma_bf16(acc[i][j], Ah[i], Bh);
                    mma_bf16(acc[i][j], Ah[i], Bl);
                    mma_bf16(acc[i][j], Al[i], Bh);
                }
            }
        }
    };

    // ---- prologue ----
    loadA(0);
    cpB(0, 0);
    CP_COMMIT();
    stsA(0);
    CP_WAIT0();
    __syncthreads();

    // ---- GEMM1 mainloop ----
    for (int c = 0; c < NCHUNK; c++) {
        const int cur = c & 1, nxt = cur ^ 1;
        if (c + 1 < NCHUNK) {
            loadA(c + 1);
            cpB(c + 1, nxt);
            CP_COMMIT();
        }
        mmaChunk(cur);
        if (c + 1 < NCHUNK) {
            stsA(nxt);
            CP_WAIT0();
        }
        __syncthreads();
    }

    // ---- epilogue 1: ReLU + split-bf16 -> sH ----
    #pragma unroll
    for (int i = 0; i < 2; i++) {
        const int r1 = wm * 32 + i * 16 + grp;
        #pragma unroll
        for (int j = 0; j < 8; j++) {
            const int col = wn * 64 + j * 8 + tid4 * 2;
            const float f0 = fmaxf(acc[i][j][0], 0.f), f1 = fmaxf(acc[i][j][1], 0.f);
            const float f2 = fmaxf(acc[i][j][2], 0.f), f3 = fmaxf(acc[i][j][3], 0.f);
            const uint32_t h0 = pack_bf2(f0, f1);
            const uint32_t l0 = pack_bf2(f0 - bf_lo(h0), f1 - bf_hi(h0));
            const uint32_t h1w = pack_bf2(f2, f3);
            const uint32_t l1w = pack_bf2(f2 - bf_lo(h1w), f3 - bf_hi(h1w));
            const int o1 = r1 * HPAD + col;
            const int o2 = o1 + 8 * HPAD;
            *(uint32_t*)(dsm + SH_HI + o1 * 2) = h0;
            *(uint32_t*)(dsm + SH_LO + o1 * 2) = l0;
            *(uint32_t*)(dsm + SH_HI + o2 * 2) = h1w;
            *(uint32_t*)(dsm + SH_LO + o2 * 2) = l1w;
        }
    }
    // ---- W2 images -> sW (48 rows) ----
    {
        const int n  = tid >> 3;
        const int kq = (tid & 7) * 32;
        if (n < N2) {
            #pragma unroll
            for (int q = 0; q < 4; q++) {
                const uint4 vh = *(const uint4*)(g_w2t_hi + n * HID + kq + q * 8);
                const uint4 vl = *(const uint4*)(g_w2t_lo + n * HID + kq + q * 8);
                *(uint4*)(dsm + SW_HI + (n * HPAD + kq + q * 8) * 2) = vh;
                *(uint4*)(dsm + SW_LO + (n * HPAD + kq + q * 8) * 2) = vl;
            }
        }
    }
    __syncthreads();

    // ---- GEMM2: all 16 warps; warp = (row group wid&7) x (n-half wid>>3) ----
    {
        const int rg = wid & 7;       // 8 row groups of 16
        const int nh = wid >> 3;      // 0: cols 0..23, 1: cols 24..47
        float acc2[3][4];
        #pragma unroll
        for (int j = 0; j < 3; j++)
            #pragma unroll
            for (int q = 0; q < 4; q++)
                acc2[j][q] = 0.f;

        #pragma unroll
        for (int s = 0; s < 16; s++) {
            const int kk = s * 16 + tid4 * 2;
            const int o1 = (rg * 16 + grp) * HPAD + kk;
            const int o2 = o1 + 8 * HPAD;
            uint32_t Ah[4], Al[4];
            Ah[0] = *(const uint32_t*)(dsm + SH_HI + o1 * 2);
            Ah[1] = *(const uint32_t*)(dsm + SH_HI + o2 * 2);
            Ah[2] = *(const uint32_t*)(dsm + SH_HI + (o1 + 8) * 2);
            Ah[3] = *(const uint32_t*)(dsm + SH_HI + (o2 + 8) * 2);
            Al[0] = *(const uint32_t*)(dsm + SH_LO + o1 * 2);
            Al[1] = *(const uint32_t*)(dsm + SH_LO + o2 * 2);
            Al[2] = *(const uint32_t*)(dsm + SH_LO + (o1 + 8) * 2);
            Al[3] = *(const uint32_t*)(dsm + SH_LO + (o2 + 8) * 2);
            #pragma unroll
            for (int j = 0; j < 3; j++) {
                const int ob = ((nh * 3 + j) * 8 + grp) * HPAD + kk;
                uint32_t Bh[2], Bl[2];
                Bh[0] = *(const uint32_t*)(dsm + SW_HI + ob * 2);
                Bh[1] = *(const uint32_t*)(dsm + SW_HI + (ob + 8) * 2);
                Bl[0] = *(const uint32_t*)(dsm + SW_LO + ob * 2);
                Bl[1] = *(const uint32_t*)(dsm + SW_LO + (ob + 8) * 2);
                mma_bf16(acc2[j], Ah, Bh);
                mma_bf16(acc2[j], Ah, Bl);
                mma_bf16(acc2[j], Al, Bh);
            }
        }

        // ---- epilogue 2: h2 = D2 + b2 ; g_h2 = h2 ; out = alpha*h2 ----
        const int r1 = blockRow + rg * 16 + grp;
        const int r2 = r1 + 8;
        #pragma unroll
        for (int j = 0; j < 3; j++) {
            const int col = (nh * 3 + j) * 8 + tid4 * 2;
            if (col >= C_OUT) continue;       // cols 40..47 are padding
            const float b0 = s_b2[col], b1v = s_b2[col + 1];
            if (r1 < N_NODES) {
                const float v0 = acc2[j][0] + b0, v1 = acc2[j][1] + b1v;
                *(float2*)(g_h2 + (size_t)r1 * C_OUT + col) = make_float2(v0, v1);
                *(float2*)(out  + (size_t)r1 * C_OUT + col) = make_float2(ALPHA0 * v0, ALPHA0 * v1);
            }
            if (r2 < N_NODES) {
                const float v2 = acc2[j][2] + b0, v3 = acc2[j][3] + b1v;
                *(float2*)(g_h2 + (size_t)r2 * C_OUT + col) = make_float2(v2, v3);
                *(float2*)(out  + (size_t)r2 * C_OUT + col) = make_float2(ALPHA0 * v2, ALPHA0 * v3);
            }
        }
    }
}

// ---------------------------------------------------------------------------
// Edge scatter-add: one thread per edge, 10 unrolled gather+red.v4 pairs.
// Indices read once per edge (coalesced); gathers have MLP=10.
// ---------------------------------------------------------------------------
__global__ void __launch_bounds__(256) edge_kernel(
    const int* __restrict__ erow,
    const int* __restrict__ ecol,
    const float* __restrict__ eval,
    float* __restrict__ out,
    long long num_edges)
{
    const long long e = (long long)blockIdx.x * blockDim.x + threadIdx.x;
    if (e >= num_edges) return;

    const int r = erow[e];
    const int c = ecol[e];
    const float v = eval[e];

    const float4* hp = reinterpret_cast<const float4*>(g_h2 + (size_t)c * C_OUT);
    float* o = out + (size_t)r * C_OUT;

    float4 h[10];
    #pragma unroll
    for (int s = 0; s < 10; s++) h[s] = __ldg(&hp[s]);

    #pragma unroll
    for (int s = 0; s < 10; s++) {
        asm volatile("red.global.add.v4.f32 [%0], {%1, %2, %3, %4};"
                     :: "l"(o + s * 4),
                        "f"(v * h[s].x), "f"(v * h[s].y), "f"(v * h[s].z), "f"(v * h[s].w)
                     : "memory");
    }
}

// ---------------------------------------------------------------------------
// log_softmax over C=40, one warp per row, in place.
// ---------------------------------------------------------------------------
__global__ void __launch_bounds__(256) logsoftmax_kernel(float* __restrict__ out)
{
    const int warp = (blockIdx.x * blockDim.x + threadIdx.x) >> 5;
    const int lane = threadIdx.x & 31;
    if (warp >= N_NODES) return;

    float* row = out + (size_t)warp * C_OUT;
    const float v0 = (lane < C_OUT) ? row[lane] : -__int_as_float(0x7f800000);
    const float v1 = (lane + 32 < C_OUT) ? row[lane + 32] : -__int_as_float(0x7f800000);

    float m = fmaxf(v0, v1);
    #pragma unroll
    for (int o = 16; o > 0; o >>= 1)
        m = fmaxf(m, __shfl_xor_sync(0xffffffffu, m, o));

    float s = ((lane < C_OUT) ? expf(v0 - m) : 0.f)
            + ((lane + 32 < C_OUT) ? expf(v1 - m) : 0.f);
    #pragma unroll
    for (int o = 16; o > 0; o >>= 1)
        s += __shfl_xor_sync(0xffffffffu, s, o);

    const float lse = m + logf(s);
    if (lane < C_OUT) row[lane] = v0 - lse;
    if (lane + 32 < C_OUT) row[lane + 32] = v1 - lse;
}

// ---------------------------------------------------------------------------
// Inputs: x, W1, b1, W2, b2, edge_row, edge_col, edge_val
// ---------------------------------------------------------------------------
extern "C" void kernel_launch(void* const* d_in, const int* in_sizes, int n_in,
                              void* d_out, int out_size)
{
    const float* x    = (const float*)d_in[0];
    const float* W1   = (const float*)d_in[1];
    const float* b1   = (const float*)d_in[2];
    const float* W2   = (const float*)d_in[3];
    const float* b2   = (const float*)d_in[4];
    const int*   erow = (const int*)d_in[5];
    const int*   ecol = (const int*)d_in[6];
    const float* eval = (const float*)d_in[7];
    float* out = (float*)d_out;

    const long long E = in_sizes[5];

    cudaFuncSetAttribute(fused_kernel,
                         cudaFuncAttributeMaxDynamicSharedMemorySize, DSMEM_BYTES);

    // prep weight images
    {
        const int total = HID * K_PAD + N2 * HID;
        prep_kernel<<<(total + 255) / 256, 256>>>(W1, b1, W2);
    }
    // fused GEMM1+GEMM2 -> g_h2, out = alpha*h2
    {
        const int blocks = (N_NODES + BM - 1) / BM;
        fused_kernel<<<blocks, 512, DSMEM_BYTES>>>(x, b2, out);
    }
    // edge scatter-add (1 thread/edge, vector red)
    {
        edge_kernel<<<(int)((E + 255) / 256), 256>>>(erow, ecol, eval, out, E);
    }
    // log_softmax
    {
        const long long threads = (long long)N_NODES * 32;
        logsoftmax_kernel<<<(int)((threads + 255) / 256), 256>>>(out);
    }
}

// round 8
// speedup vs baseline: 1.1153x; 1.1153x over previous
#include <cuda_runtime.h>
#include <cuda_bf16.h>
#include <cstdint>

#define N_NODES 100000
#define F_IN    500
#define HID     256
#define C_OUT   40
#define ALPHA0  0.1f
#define K_PAD   512
#define BK      32
#define NCHUNK  16
#define BM      128
#define N2      48

// ---------------------------------------------------------------------------
// Device-global scratch (allocation-free rule)
// ---------------------------------------------------------------------------
__device__ float g_h2[(size_t)N_NODES * C_OUT];                       // 16 MB
__device__ __align__(16) __nv_bfloat16 g_w1t_hi[HID * K_PAD];
__device__ __align__(16) __nv_bfloat16 g_w1t_lo[HID * K_PAD];
__device__ __align__(16) __nv_bfloat16 g_w2t_hi[N2 * HID];
__device__ __align__(16) __nv_bfloat16 g_w2t_lo[N2 * HID];

// ---------------------------------------------------------------------------
// Helpers
// ---------------------------------------------------------------------------
__device__ __forceinline__ uint32_t smem_u32(const void* p) {
    uint32_t a;
    asm("{ .reg .u64 t; cvta.to.shared.u64 t, %1; cvt.u32.u64 %0, t; }" : "=r"(a) : "l"(p));
    return a;
}

__device__ __forceinline__ uint32_t pack_bf2(float lo, float hi) {
    uint32_t r;
    asm("cvt.rn.bf16x2.f32 %0, %1, %2;" : "=r"(r) : "f"(hi), "f"(lo));
    return r;
}
__device__ __forceinline__ float bf_lo(uint32_t w) { return __uint_as_float(w << 16); }
__device__ __forceinline__ float bf_hi(uint32_t w) { return __uint_as_float(w & 0xffff0000u); }

__device__ __forceinline__ void mma_bf16(float d[4], const uint32_t a[4], const uint32_t b[2]) {
    asm volatile("mma.sync.aligned.m16n8k16.row.col.f32.bf16.bf16.f32 "
                 "{%0,%1,%2,%3},{%4,%5,%6,%7},{%8,%9},{%0,%1,%2,%3};"
                 : "+f"(d[0]), "+f"(d[1]), "+f"(d[2]), "+f"(d[3])
                 : "r"(a[0]), "r"(a[1]), "r"(a[2]), "r"(a[3]), "r"(b[0]), "r"(b[1]));
}

#define CP_ASYNC16(dst, src) \
    asm volatile("cp.async.cg.shared.global [%0], [%1], 16;" :: "r"(dst), "l"(src))
#define CP_COMMIT() asm volatile("cp.async.commit_group;" ::: "memory")
#define CP_WAIT0()  asm volatile("cp.async.wait_group 0;" ::: "memory")

// ---------------------------------------------------------------------------
// Dynamic SMEM layout (bytes)
// ---------------------------------------------------------------------------
#define APAD 40
#define SA_HI(b) ((b) * 61440)
#define SA_LO(b) ((b) * 61440 + 10240)
#define SB_HI(b) ((b) * 61440 + 20480)
#define SB_LO(b) ((b) * 61440 + 40960)
#define HPAD 264
#define SH_HI 0
#define SH_LO 67584
#define SW_HI 135168
#define SW_LO 160512
#define DSMEM_BYTES 185856

// ---------------------------------------------------------------------------
// Prep: bf16 hi/lo images of W1^T (bias folded at k=500) and W2^T (pad 40->48)
// ---------------------------------------------------------------------------
__global__ void prep_kernel(const float* __restrict__ W1,
                            const float* __restrict__ b1,
                            const float* __restrict__ W2)
{
    const int idx = blockIdx.x * blockDim.x + threadIdx.x;
    if (idx < HID * K_PAD) {
        const int n = idx >> 9;
        const int k = idx & (K_PAD - 1);
        float v = 0.f;
        if (k < F_IN)       v = W1[(size_t)k * HID + n];
        else if (k == F_IN) v = b1[n];
        const __nv_bfloat16 h = __float2bfloat16_rn(v);
        g_w1t_hi[idx] = h;
        g_w1t_lo[idx] = __float2bfloat16_rn(v - __bfloat162float(h));
    } else {
        const int i = idx - HID * K_PAD;
        if (i < N2 * HID) {
            const int n = i >> 8;
            const int k = i & 255;
            const float v = (n < C_OUT) ? W2[(size_t)k * C_OUT + n] : 0.f;
            const __nv_bfloat16 h = __float2bfloat16_rn(v);
            g_w2t_hi[i] = h;
            g_w2t_lo[i] = __float2bfloat16_rn(v - __bfloat162float(h));
        }
    }
}

// ---------------------------------------------------------------------------
// Fused GEMM1(+bias+ReLU)+GEMM2(+bias), mma.sync bf16 split (3 terms).
// 512 threads / 16 warps; GEMM1 warp tile 32x64; GEMM2 split over all 16 warps.
// ---------------------------------------------------------------------------
__global__ void __launch_bounds__(512, 1) fused_kernel(
    const float* __restrict__ x,
    const float* __restrict__ b2,
    float* __restrict__ out)
{
    extern __shared__ char dsm[];
    __shared__ float s_b2[C_OUT];
    const uint32_t smbase = smem_u32(dsm);
    const int tid  = threadIdx.x;
    const int lane = tid & 31, wid = tid >> 5;
    const int grp  = lane >> 2, tid4 = lane & 3;
    const int wm   = wid >> 2, wn = wid & 3;      // GEMM1: wm,wn in 0..3
    const int blockRow = blockIdx.x * BM;

    if (tid < C_OUT) s_b2[tid] = b2[tid];

    // A global-load mapping: 128 rows x 4 threads, 8 floats each
    const int ar  = tid >> 2;
    const int akq = (tid & 3) * 8;

    // B cp.async mapping: 256 rows x 2 threads, 16B each
    const int brow = tid >> 1;
    const int bseg = tid & 1;

    float acc[2][8][4];
    #pragma unroll
    for (int i = 0; i < 2; i++)
        #pragma unroll
        for (int j = 0; j < 8; j++)
            #pragma unroll
            for (int q = 0; q < 4; q++)
                acc[i][j][q] = 0.f;

    const int grow = blockRow + ar;
    const bool rok = grow < N_NODES;
    const float* xrow = x + (size_t)grow * F_IN;

    float4 av[2];

    auto loadA = [&](int c) {
        const int gk0 = c * BK + akq;
        #pragma unroll
        for (int h = 0; h < 2; h++) {
            const int gk = gk0 + h * 4;
            float4 v = make_float4(0.f, 0.f, 0.f, 0.f);
            if (rok) {
                if (gk + 3 < F_IN) {
                    v = *(const float4*)(xrow + gk);
                } else {
                    v.x = (gk + 0 < F_IN) ? xrow[gk + 0] : (gk + 0 == F_IN ? 1.f : 0.f);
                    v.y = (gk + 1 < F_IN) ? xrow[gk + 1] : (gk + 1 == F_IN ? 1.f : 0.f);
                    v.z = (gk + 2 < F_IN) ? xrow[gk + 2] : (gk + 2 == F_IN ? 1.f : 0.f);
                    v.w = (gk + 3 < F_IN) ? xrow[gk + 3] : (gk + 3 == F_IN ? 1.f : 0.f);
                }
            }
            av[h] = v;
        }
    };
    auto stsA = [&](int buf) {
        #pragma unroll
        for (int h = 0; h < 2; h++) {
            const int o = ar * APAD + akq + h * 4;
            const uint32_t h0 = pack_bf2(av[h].x, av[h].y);
            const uint32_t h1 = pack_bf2(av[h].z, av[h].w);
            const uint32_t l0 = pack_bf2(av[h].x - bf_lo(h0), av[h].y - bf_hi(h0));
            const uint32_t l1 = pack_bf2(av[h].z - bf_lo(h1), av[h].w - bf_hi(h1));
            *(uint2*)(dsm + SA_HI(buf) + o * 2) = make_uint2(h0, h1);
            *(uint2*)(dsm + SA_LO(buf) + o * 2) = make_uint2(l0, l1);
        }
    };
    auto cpB = [&](int c, int buf) {
        const uint32_t dhi = smbase + SB_HI(buf) + brow * (APAD * 2) + bseg * 16;
        const uint32_t dlo = smbase + SB_LO(buf) + brow * (APAD * 2) + bseg * 16;
        const __nv_bfloat16* shi = g_w1t_hi + (size_t)brow * K_PAD + c * BK + bseg * 8;
        const __nv_bfloat16* slo = g_w1t_lo + (size_t)brow * K_PAD + c * BK + bseg * 8;
        CP_ASYNC16(dhi, shi);
        CP_ASYNC16(dhi + 32, shi + 16);
        CP_ASYNC16(dlo, slo);
        CP_ASYNC16(dlo + 32, slo + 16);
    };
    auto mmaChunk = [&](int buf) {
        #pragma unroll
        for (int s = 0; s < 2; s++) {
            const int kk = s * 16 + tid4 * 2;
            uint32_t Ah[2][4], Al[2][4];
            #pragma unroll
            for (int i = 0; i < 2; i++) {
                const int o1 = (wm * 32 + i * 16 + grp) * APAD + kk;
                const int o2 = o1 + 8 * APAD;
                Ah[i][0] = *(const uint32_t*)(dsm + SA_HI(buf) + o1 * 2);
                Ah[i][1] = *(const uint32_t*)(dsm + SA_HI(buf) + o2 * 2);
                Ah[i][2] = *(const uint32_t*)(dsm + SA_HI(buf) + (o1 + 8) * 2);
                Ah[i][3] = *(const uint32_t*)(dsm + SA_HI(buf) + (o2 + 8) * 2);
                Al[i][0] = *(const uint32_t*)(dsm + SA_LO(buf) + o1 * 2);
                Al[i][1] = *(const uint32_t*)(dsm + SA_LO(buf) + o2 * 2);
                Al[i][2] = *(const uint32_t*)(dsm + SA_LO(buf) + (o1 + 8) * 2);
                Al[i][3] = *(const uint32_t*)(dsm + SA_LO(buf) + (o2 + 8) * 2);
            }
            #pragma unroll
            for (int j = 0; j < 8; j++) {
                const int o = (wn * 64 + j * 8 + grp) * APAD + kk;
                uint32_t Bh[2], Bl[2];
                Bh[0] = *(const uint32_t*)(dsm + SB_HI(buf) + o * 2);
                Bh[1] = *(const uint32_t*)(dsm + SB_HI(buf) + (o + 8) * 2);
                Bl[0] = *(const uint32_t*)(dsm + SB_LO(buf) + o * 2);
                Bl[1] = *(const uint32_t*)(dsm + SB_LO(buf) + (o + 8) * 2);
                #pragma unroll
                for (int i = 0; i < 2; i++) {
                    mma_bf16(acc[i][j], Ah[i], Bh);
                    mma_bf16(acc[i][j], Ah[i], Bl);
                    mma_bf16(acc[i][j], Al[i], Bh);
                }
            }
        }
    };

    // ---- prologue ----
    loadA(0);
    cpB(0, 0);
    CP_COMMIT();
    stsA(0);
    CP_WAIT0();
    __syncthreads();

    // ---- GEMM1 mainloop ----
    for (int c = 0; c < NCHUNK; c++) {
        const int cur = c & 1, nxt = cur ^ 1;
        if (c + 1 < NCHUNK) {
            loadA(c + 1);
            cpB(c + 1, nxt);
            CP_COMMIT();
        }
        mmaChunk(cur);
        if (c + 1 < NCHUNK) {
            stsA(nxt);
            CP_WAIT0();
        }
        __syncthreads();
    }

    // ---- epilogue 1: ReLU + split-bf16 -> sH ----
    #pragma unroll
    for (int i = 0; i < 2; i++) {
        const int r1 = wm * 32 + i * 16 + grp;
        #pragma unroll
        for (int j = 0; j < 8; j++) {
            const int col = wn * 64 + j * 8 + tid4 * 2;
            const float f0 = fmaxf(acc[i][j][0], 0.f), f1 = fmaxf(acc[i][j][1], 0.f);
            const float f2 = fmaxf(acc[i][j][2], 0.f), f3 = fmaxf(acc[i][j][3], 0.f);
            const uint32_t h0 = pack_bf2(f0, f1);
            const uint32_t l0 = pack_bf2(f0 - bf_lo(h0), f1 - bf_hi(h0));
            const uint32_t h1w = pack_bf2(f2, f3);
            const uint32_t l1w = pack_bf2(f2 - bf_lo(h1w), f3 - bf_hi(h1w));
            const int o1 = r1 * HPAD + col;
            const int o2 = o1 + 8 * HPAD;
            *(uint32_t*)(dsm + SH_HI + o1 * 2) = h0;
            *(uint32_t*)(dsm + SH_LO + o1 * 2) = l0;
            *(uint32_t*)(dsm + SH_HI + o2 * 2) = h1w;
            *(uint32_t*)(dsm + SH_LO + o2 * 2) = l1w;
        }
    }
    // ---- W2 images -> sW (48 rows) ----
    {
        const int n  = tid >> 3;
        const int kq = (tid & 7) * 32;
        if (n < N2) {
            #pragma unroll
            for (int q = 0; q < 4; q++) {
                const uint4 vh = *(const uint4*)(g_w2t_hi + n * HID + kq + q * 8);
                const uint4 vl = *(const uint4*)(g_w2t_lo + n * HID + kq + q * 8);
                *(uint4*)(dsm + SW_HI + (n * HPAD + kq + q * 8) * 2) = vh;
                *(uint4*)(dsm + SW_LO + (n * HPAD + kq + q * 8) * 2) = vl;
            }
        }
    }
    __syncthreads();

    // ---- GEMM2: all 16 warps; warp = (row group wid&7) x (n-half wid>>3) ----
    {
        const int rg = wid & 7;       // 8 row groups of 16
        const int nh = wid >> 3;      // 0: cols 0..23, 1: cols 24..47
        float acc2[3][4];
        #pragma unroll
        for (int j = 0; j < 3; j++)
            #pragma unroll
            for (int q = 0; q < 4; q++)
                acc2[j][q] = 0.f;

        #pragma unroll
        for (int s = 0; s < 16; s++) {
            const int kk = s * 16 + tid4 * 2;
            const int o1 = (rg * 16 + grp) * HPAD + kk;
            const int o2 = o1 + 8 * HPAD;
            uint32_t Ah[4], Al[4];
            Ah[0] = *(const uint32_t*)(dsm + SH_HI + o1 * 2);
            Ah[1] = *(const uint32_t*)(dsm + SH_HI + o2 * 2);
            Ah[2] = *(const uint32_t*)(dsm + SH_HI + (o1 + 8) * 2);
            Ah[3] = *(const uint32_t*)(dsm + SH_HI + (o2 + 8) * 2);
            Al[0] = *(const uint32_t*)(dsm + SH_LO + o1 * 2);
            Al[1] = *(const uint32_t*)(dsm + SH_LO + o2 * 2);
            Al[2] = *(const uint32_t*)(dsm + SH_LO + (o1 + 8) * 2);
            Al[3] = *(const uint32_t*)(dsm + SH_LO + (o2 + 8) * 2);
            #pragma unroll
            for (int j = 0; j < 3; j++) {
                const int ob = ((nh * 3 + j) * 8 + grp) * HPAD + kk;
                uint32_t Bh[2], Bl[2];
                Bh[0] = *(const uint32_t*)(dsm + SW_HI + ob * 2);
                Bh[1] = *(const uint32_t*)(dsm + SW_HI + (ob + 8) * 2);
                Bl[0] = *(const uint32_t*)(dsm + SW_LO + ob * 2);
                Bl[1] = *(const uint32_t*)(dsm + SW_LO + (ob + 8) * 2);
                mma_bf16(acc2[j], Ah, Bh);
                mma_bf16(acc2[j], Ah, Bl);
                mma_bf16(acc2[j], Al, Bh);
            }
        }

        // ---- epilogue 2: h2 = D2 + b2 ; g_h2 = h2 ; out = alpha*h2 ----
        const int r1 = blockRow + rg * 16 + grp;
        const int r2 = r1 + 8;
        #pragma unroll
        for (int j = 0; j < 3; j++) {
            const int col = (nh * 3 + j) * 8 + tid4 * 2;
            if (col >= C_OUT) continue;       // cols 40..47 are padding
            const float b0 = s_b2[col], b1v = s_b2[col + 1];
            if (r1 < N_NODES) {
                const float v0 = acc2[j][0] + b0, v1 = acc2[j][1] + b1v;
                *(float2*)(g_h2 + (size_t)r1 * C_OUT + col) = make_float2(v0, v1);
                *(float2*)(out  + (size_t)r1 * C_OUT + col) = make_float2(ALPHA0 * v0, ALPHA0 * v1);
            }
            if (r2 < N_NODES) {
                const float v2 = acc2[j][2] + b0, v3 = acc2[j][3] + b1v;
                *(float2*)(g_h2 + (size_t)r2 * C_OUT + col) = make_float2(v2, v3);
                *(float2*)(out  + (size_t)r2 * C_OUT + col) = make_float2(ALPHA0 * v2, ALPHA0 * v3);
            }
        }
    }
}

// ---------------------------------------------------------------------------
// Edge scatter-add: out[row] += val * h2[col]  (10 threads/edge, red.v4)
// Coalesced: 10 consecutive lanes read consecutive float4s of the same row.
// ---------------------------------------------------------------------------
__global__ void __launch_bounds__(256) edge_kernel(
    const int* __restrict__ erow,
    const int* __restrict__ ecol,
    const float* __restrict__ eval,
    float* __restrict__ out,
    long long num_edges)
{
    const long long gid = (long long)blockIdx.x * blockDim.x + threadIdx.x;
    const long long e = gid / 10;
    if (e >= num_edges) return;
    const int sub = (int)(gid % 10);

    const int r = erow[e];
    const int c = ecol[e];
    const float v = eval[e];

    const float4 h = reinterpret_cast<const float4*>(g_h2 + (size_t)c * C_OUT)[sub];
    float* o = out + (size_t)r * C_OUT + sub * 4;
    asm volatile("red.global.add.v4.f32 [%0], {%1, %2, %3, %4};"
                 :: "l"(o), "f"(v * h.x), "f"(v * h.y), "f"(v * h.z), "f"(v * h.w)
                 : "memory");
}

// ---------------------------------------------------------------------------
// log_softmax over C=40, one warp per row, in place.
// ---------------------------------------------------------------------------
__global__ void __launch_bounds__(256) logsoftmax_kernel(float* __restrict__ out)
{
    const int warp = (blockIdx.x * blockDim.x + threadIdx.x) >> 5;
    const int lane = threadIdx.x & 31;
    if (warp >= N_NODES) return;

    float* row = out + (size_t)warp * C_OUT;
    const float v0 = (lane < C_OUT) ? row[lane] : -__int_as_float(0x7f800000);
    const float v1 = (lane + 32 < C_OUT) ? row[lane + 32] : -__int_as_float(0x7f800000);

    float m = fmaxf(v0, v1);
    #pragma unroll
    for (int o = 16; o > 0; o >>= 1)
        m = fmaxf(m, __shfl_xor_sync(0xffffffffu, m, o));

    float s = ((lane < C_OUT) ? expf(v0 - m) : 0.f)
            + ((lane + 32 < C_OUT) ? expf(v1 - m) : 0.f);
    #pragma unroll
    for (int o = 16; o > 0; o >>= 1)
        s += __shfl_xor_sync(0xffffffffu, s, o);

    const float lse = m + logf(s);
    if (lane < C_OUT) row[lane] = v0 - lse;
    if (lane + 32 < C_OUT) row[lane + 32] = v1 - lse;
}

// ---------------------------------------------------------------------------
// Inputs: x, W1, b1, W2, b2, edge_row, edge_col, edge_val
// ---------------------------------------------------------------------------
extern "C" void kernel_launch(void* const* d_in, const int* in_sizes, int n_in,
                              void* d_out, int out_size)
{
    const float* x    = (const float*)d_in[0];
    const float* W1   = (const float*)d_in[1];
    const float* b1   = (const float*)d_in[2];
    const float* W2   = (const float*)d_in[3];
    const float* b2   = (const float*)d_in[4];
    const int*   erow = (const int*)d_in[5];
    const int*   ecol = (const int*)d_in[6];
    const float* eval = (const float*)d_in[7];
    float* out = (float*)d_out;

    const long long E = in_sizes[5];

    cudaFuncSetAttribute(fused_kernel,
                         cudaFuncAttributeMaxDynamicSharedMemorySize, DSMEM_BYTES);

    // prep weight images
    {
        const int total = HID * K_PAD + N2 * HID;
        prep_kernel<<<(total + 255) / 256, 256>>>(W1, b1, W2);
    }
    // fused GEMM1+GEMM2 -> g_h2, out = alpha*h2
    {
        const int blocks = (N_NODES + BM - 1) / BM;
        fused_kernel<<<blocks, 512, DSMEM_BYTES>>>(x, b2, out);
    }
    // edge scatter-add (10 threads/edge, vector red)
    {
        const long long total = E * 10;
        edge_kernel<<<(int)((total + 255) / 256), 256>>>(erow, ecol, eval, out, E);
    }
    // log_softmax
    {
        const long long threads = (long long)N_NODES * 32;
        logsoftmax_kernel<<<(int)((threads + 255) / 256), 256>>>(out);
    }
}

// round 9
// speedup vs baseline: 1.5063x; 1.3506x over previous
#include <cuda_runtime.h>
#include <cuda_fp16.h>
#include <cstdint>

#define N_NODES 100000
#define F_IN    500
#define HID     256
#define C_OUT   40
#define ALPHA0  0.1f
#define K_PAD   512
#define BK      32
#define NCHUNK  16
#define BM      128
#define N2      48

// ---------------------------------------------------------------------------
// Device-global scratch (allocation-free rule)
// ---------------------------------------------------------------------------
__device__ float g_h2[(size_t)N_NODES * C_OUT];            // 16 MB
__device__ __align__(16) __half g_w1t[HID * K_PAD];        // W1^T fp16 (bias at k=500)
__device__ __align__(16) __half g_w2t[N2 * HID];           // W2^T fp16 (n padded 40->48)

// ---------------------------------------------------------------------------
// Helpers
// ---------------------------------------------------------------------------
__device__ __forceinline__ uint32_t smem_u32(const void* p) {
    uint32_t a;
    asm("{ .reg .u64 t; cvta.to.shared.u64 t, %1; cvt.u32.u64 %0, t; }" : "=r"(a) : "l"(p));
    return a;
}

// pack (lo, hi) floats into f16x2 word: lower halfword = lo
__device__ __forceinline__ uint32_t pack_h2(float lo, float hi) {
    uint32_t r;
    asm("cvt.rn.f16x2.f32 %0, %1, %2;" : "=r"(r) : "f"(hi), "f"(lo));
    return r;
}
__device__ __forceinline__ float h2_lo(uint32_t w) {
    const __half2 h = *reinterpret_cast<const __half2*>(&w);
    return __half2float(__low2half(h));
}
__device__ __forceinline__ float h2_hi(uint32_t w) {
    const __half2 h = *reinterpret_cast<const __half2*>(&w);
    return __half2float(__high2half(h));
}

__device__ __forceinline__ void mma_f16(float d[4], const uint32_t a[4], const uint32_t b[2]) {
    asm volatile("mma.sync.aligned.m16n8k16.row.col.f32.f16.f16.f32 "
                 "{%0,%1,%2,%3},{%4,%5,%6,%7},{%8,%9},{%0,%1,%2,%3};"
                 : "+f"(d[0]), "+f"(d[1]), "+f"(d[2]), "+f"(d[3])
                 : "r"(a[0]), "r"(a[1]), "r"(a[2]), "r"(a[3]), "r"(b[0]), "r"(b[1]));
}

#define CP_ASYNC16(dst, src) \
    asm volatile("cp.async.cg.shared.global [%0], [%1], 16;" :: "r"(dst), "l"(src))
#define CP_COMMIT() asm volatile("cp.async.commit_group;" ::: "memory")
#define CP_WAIT0()  asm volatile("cp.async.wait_group 0;" ::: "memory")

// ---------------------------------------------------------------------------
// Dynamic SMEM layout (bytes)
// Stage 1, two buffers of 40960B: sA_hi[128][40]f16 | sA_lo | sB[256][40]f16
// Stage 2 (reuses region): sH_hi[128][264] | sH_lo | sW[48][264]
// ---------------------------------------------------------------------------
#define APAD 40
#define SA_HI(b) ((b) * 40960)
#define SA_LO(b) ((b) * 40960 + 10240)
#define SB(b)    ((b) * 40960 + 20480)
#define HPAD 264
#define SH_HI 0
#define SH_LO 67584
#define SW    135168
#define DSMEM_BYTES 160512

// ---------------------------------------------------------------------------
// Prep: fp16 images of W1^T (bias folded at k=500) and W2^T (pad 40->48)
// ---------------------------------------------------------------------------
__global__ void prep_kernel(const float* __restrict__ W1,
                            const float* __restrict__ b1,
                            const float* __restrict__ W2)
{
    const int idx = blockIdx.x * blockDim.x + threadIdx.x;
    if (idx < HID * K_PAD) {
        const int n = idx >> 9;
        const int k = idx & (K_PAD - 1);
        float v = 0.f;
        if (k < F_IN)       v = W1[(size_t)k * HID + n];
        else if (k == F_IN) v = b1[n];
        g_w1t[idx] = __float2half_rn(v);
    } else {
        const int i = idx - HID * K_PAD;
        if (i < N2 * HID) {
            const int n = i >> 8;
            const int k = i & 255;
            const float v = (n < C_OUT) ? W2[(size_t)k * C_OUT + n] : 0.f;
            g_w2t[i] = __float2half_rn(v);
        }
    }
}

// ---------------------------------------------------------------------------
// Fused GEMM1(+bias+ReLU)+GEMM2(+bias), mma.sync fp16 2-term split.
// 512 threads / 16 warps; GEMM1 warp tile 32x64; GEMM2 split over all 16 warps.
// ---------------------------------------------------------------------------
__global__ void __launch_bounds__(512, 1) fused_kernel(
    const float* __restrict__ x,
    const float* __restrict__ b2,
    float* __restrict__ out)
{
    extern __shared__ char dsm[];
    __shared__ float s_b2[C_OUT];
    const uint32_t smbase = smem_u32(dsm);
    const int tid  = threadIdx.x;
    const int lane = tid & 31, wid = tid >> 5;
    const int grp  = lane >> 2, tid4 = lane & 3;
    const int wm   = wid >> 2, wn = wid & 3;      // GEMM1: wm,wn in 0..3
    const int blockRow = blockIdx.x * BM;

    if (tid < C_OUT) s_b2[tid] = b2[tid];

    // A global-load mapping: 128 rows x 4 threads, 8 floats each
    const int ar  = tid >> 2;
    const int akq = (tid & 3) * 8;

    // B cp.async mapping: 256 rows x 2 threads, 2x16B each (64B per row)
    const int brow = tid >> 1;
    const int bseg = tid & 1;

    float acc[2][8][4];
    #pragma unroll
    for (int i = 0; i < 2; i++)
        #pragma unroll
        for (int j = 0; j < 8; j++)
            #pragma unroll
            for (int q = 0; q < 4; q++)
                acc[i][j][q] = 0.f;

    const int grow = blockRow + ar;
    const bool rok = grow < N_NODES;
    const float* xrow = x + (size_t)grow * F_IN;

    float4 av[2];

    auto loadA = [&](int c) {
        const int gk0 = c * BK + akq;
        #pragma unroll
        for (int h = 0; h < 2; h++) {
            const int gk = gk0 + h * 4;
            float4 v = make_float4(0.f, 0.f, 0.f, 0.f);
            if (rok) {
                if (gk + 3 < F_IN) {
                    v = *(const float4*)(xrow + gk);
                } else {
                    v.x = (gk + 0 < F_IN) ? xrow[gk + 0] : (gk + 0 == F_IN ? 1.f : 0.f);
                    v.y = (gk + 1 < F_IN) ? xrow[gk + 1] : (gk + 1 == F_IN ? 1.f : 0.f);
                    v.z = (gk + 2 < F_IN) ? xrow[gk + 2] : (gk + 2 == F_IN ? 1.f : 0.f);
                    v.w = (gk + 3 < F_IN) ? xrow[gk + 3] : (gk + 3 == F_IN ? 1.f : 0.f);
                }
            }
            av[h] = v;
        }
    };
    auto stsA = [&](int buf) {
        #pragma unroll
        for (int h = 0; h < 2; h++) {
            const int o = ar * APAD + akq + h * 4;
            const uint32_t h0 = pack_h2(av[h].x, av[h].y);
            const uint32_t h1 = pack_h2(av[h].z, av[h].w);
            const uint32_t l0 = pack_h2(av[h].x - h2_lo(h0), av[h].y - h2_hi(h0));
            const uint32_t l1 = pack_h2(av[h].z - h2_lo(h1), av[h].w - h2_hi(h1));
            *(uint2*)(dsm + SA_HI(buf) + o * 2) = make_uint2(h0, h1);
            *(uint2*)(dsm + SA_LO(buf) + o * 2) = make_uint2(l0, l1);
        }
    };
    auto cpB = [&](int c, int buf) {
        const uint32_t d0 = smbase + SB(buf) + brow * (APAD * 2) + bseg * 16;
        const __half* s0 = g_w1t + (size_t)brow * K_PAD + c * BK + bseg * 8;
        CP_ASYNC16(d0, s0);
        CP_ASYNC16(d0 + 32, s0 + 16);
    };
    auto mmaChunk = [&](int buf) {
        #pragma unroll
        for (int s = 0; s < 2; s++) {
            const int kk = s * 16 + tid4 * 2;
            uint32_t Ah[2][4], Al[2][4];
            #pragma unroll
            for (int i = 0; i < 2; i++) {
                const int o1 = (wm * 32 + i * 16 + grp) * APAD + kk;
                const int o2 = o1 + 8 * APAD;
                Ah[i][0] = *(const uint32_t*)(dsm + SA_HI(buf) + o1 * 2);
                Ah[i][1] = *(const uint32_t*)(dsm + SA_HI(buf) + o2 * 2);
                Ah[i][2] = *(const uint32_t*)(dsm + SA_HI(buf) + (o1 + 8) * 2);
                Ah[i][3] = *(const uint32_t*)(dsm + SA_HI(buf) + (o2 + 8) * 2);
                Al[i][0] = *(const uint32_t*)(dsm + SA_LO(buf) + o1 * 2);
                Al[i][1] = *(const uint32_t*)(dsm + SA_LO(buf) + o2 * 2);
                Al[i][2] = *(const uint32_t*)(dsm + SA_LO(buf) + (o1 + 8) * 2);
                Al[i][3] = *(const uint32_t*)(dsm + SA_LO(buf) + (o2 + 8) * 2);
            }
            #pragma unroll
            for (int j = 0; j < 8; j++) {
                const int o = (wn * 64 + j * 8 + grp) * APAD + kk;
                uint32_t B[2];
                B[0] = *(const uint32_t*)(dsm + SB(buf) + o * 2);
                B[1] = *(const uint32_t*)(dsm + SB(buf) + (o + 8) * 2);
                #pragma unroll
                for (int i = 0; i < 2; i++) {
                    mma_f16(acc[i][j], Ah[i], B);
                    mma_f16(acc[i][j], Al[i], B);
                }
            }
        }
    };

    // ---- prologue ----
    loadA(0);
    cpB(0, 0);
    CP_COMMIT();
    stsA(0);
    CP_WAIT0();
    __syncthreads();

    // ---- GEMM1 mainloop ----
    for (int c = 0; c < NCHUNK; c++) {
        const int cur = c & 1, nxt = cur ^ 1;
        if (c + 1 < NCHUNK) {
            loadA(c + 1);
            cpB(c + 1, nxt);
            CP_COMMIT();
        }
        mmaChunk(cur);
        if (c + 1 < NCHUNK) {
            stsA(nxt);
            CP_WAIT0();
        }
        __syncthreads();
    }

    // ---- epilogue 1: ReLU + fp16 hi/lo split -> sH ----
    #pragma unroll
    for (int i = 0; i < 2; i++) {
        const int r1 = wm * 32 + i * 16 + grp;
        #pragma unroll
        for (int j = 0; j < 8; j++) {
            const int col = wn * 64 + j * 8 + tid4 * 2;
            const float f0 = fmaxf(acc[i][j][0], 0.f), f1 = fmaxf(acc[i][j][1], 0.f);
            const float f2 = fmaxf(acc[i][j][2], 0.f), f3 = fmaxf(acc[i][j][3], 0.f);
            const uint32_t h0 = pack_h2(f0, f1);
            const uint32_t l0 = pack_h2(f0 - h2_lo(h0), f1 - h2_hi(h0));
            const uint32_t h1w = pack_h2(f2, f3);
            const uint32_t l1w = pack_h2(f2 - h2_lo(h1w), f3 - h2_hi(h1w));
            const int o1 = r1 * HPAD + col;
            const int o2 = o1 + 8 * HPAD;
            *(uint32_t*)(dsm + SH_HI + o1 * 2) = h0;
            *(uint32_t*)(dsm + SH_LO + o1 * 2) = l0;
            *(uint32_t*)(dsm + SH_HI + o2 * 2) = h1w;
            *(uint32_t*)(dsm + SH_LO + o2 * 2) = l1w;
        }
    }
    // ---- W2 image -> sW (48 rows, fp16) ----
    {
        const int n  = tid >> 3;
        const int kq = (tid & 7) * 32;
        if (n < N2) {
            #pragma unroll
            for (int q = 0; q < 4; q++) {
                const uint4 v = *(const uint4*)(g_w2t + n * HID + kq + q * 8);
                *(uint4*)(dsm + SW + (n * HPAD + kq + q * 8) * 2) = v;
            }
        }
    }
    __syncthreads();

    // ---- GEMM2: all 16 warps; warp = (row group wid&7) x (n-half wid>>3) ----
    {
        const int rg = wid & 7;       // 8 row groups of 16
        const int nh = wid >> 3;      // 0: cols 0..23, 1: cols 24..47
        float acc2[3][4];
        #pragma unroll
        for (int j = 0; j < 3; j++)
            #pragma unroll
            for (int q = 0; q < 4; q++)
                acc2[j][q] = 0.f;

        #pragma unroll
        for (int s = 0; s < 16; s++) {
            const int kk = s * 16 + tid4 * 2;
            const int o1 = (rg * 16 + grp) * HPAD + kk;
            const int o2 = o1 + 8 * HPAD;
            uint32_t Ah[4], Al[4];
            Ah[0] = *(const uint32_t*)(dsm + SH_HI + o1 * 2);
            Ah[1] = *(const uint32_t*)(dsm + SH_HI + o2 * 2);
            Ah[2] = *(const uint32_t*)(dsm + SH_HI + (o1 + 8) * 2);
            Ah[3] = *(const uint32_t*)(dsm + SH_HI + (o2 + 8) * 2);
            Al[0] = *(const uint32_t*)(dsm + SH_LO + o1 * 2);
            Al[1] = *(const uint32_t*)(dsm + SH_LO + o2 * 2);
            Al[2] = *(const uint32_t*)(dsm + SH_LO + (o1 + 8) * 2);
            Al[3] = *(const uint32_t*)(dsm + SH_LO + (o2 + 8) * 2);
            #pragma unroll
            for (int j = 0; j < 3; j++) {
                const int ob = ((nh * 3 + j) * 8 + grp) * HPAD + kk;
                uint32_t B[2];
                B[0] = *(const uint32_t*)(dsm + SW + ob * 2);
                B[1] = *(const uint32_t*)(dsm + SW + (ob + 8) * 2);
                mma_f16(acc2[j], Ah, B);
                mma_f16(acc2[j], Al, B);
            }
        }

        // ---- epilogue 2: h2 = D2 + b2 ; g_h2 = h2 ; out = alpha*h2 ----
        const int r1 = blockRow + rg * 16 + grp;
        const int r2 = r1 + 8;
        #pragma unroll
        for (int j = 0; j < 3; j++) {
            const int col = (nh * 3 + j) * 8 + tid4 * 2;
            if (col >= C_OUT) continue;       // cols 40..47 are padding
            const float b0 = s_b2[col], b1v = s_b2[col + 1];
            if (r1 < N_NODES) {
                const float v0 = acc2[j][0] + b0, v1 = acc2[j][1] + b1v;
                *(float2*)(g_h2 + (size_t)r1 * C_OUT + col) = make_float2(v0, v1);
                *(float2*)(out  + (size_t)r1 * C_OUT + col) = make_float2(ALPHA0 * v0, ALPHA0 * v1);
            }
            if (r2 < N_NODES) {
                const float v2 = acc2[j][2] + b0, v3 = acc2[j][3] + b1v;
                *(float2*)(g_h2 + (size_t)r2 * C_OUT + col) = make_float2(v2, v3);
                *(float2*)(out  + (size_t)r2 * C_OUT + col) = make_float2(ALPHA0 * v2, ALPHA0 * v3);
            }
        }
    }
}

// ---------------------------------------------------------------------------
// Edge scatter-add: out[row] += val * h2[col]  (10 threads/edge, red.v4)
// Coalesced: 10 consecutive lanes read consecutive float4s of the same row.
// ---------------------------------------------------------------------------
__global__ void __launch_bounds__(256) edge_kernel(
    const int* __restrict__ erow,
    const int* __restrict__ ecol,
    const float* __restrict__ eval,
    float* __restrict__ out,
    long long num_edges)
{
    const long long gid = (long long)blockIdx.x * blockDim.x + threadIdx.x;
    const long long e = gid / 10;
    if (e >= num_edges) return;
    const int sub = (int)(gid % 10);

    const int r = erow[e];
    const int c = ecol[e];
    const float v = eval[e];

    const float4 h = reinterpret_cast<const float4*>(g_h2 + (size_t)c * C_OUT)[sub];
    float* o = out + (size_t)r * C_OUT + sub * 4;
    asm volatile("red.global.add.v4.f32 [%0], {%1, %2, %3, %4};"
                 :: "l"(o), "f"(v * h.x), "f"(v * h.y), "f"(v * h.z), "f"(v * h.w)
                 : "memory");
}

// ---------------------------------------------------------------------------
// log_softmax over C=40, one warp per row, in place.
// ---------------------------------------------------------------------------
__global__ void __launch_bounds__(256) logsoftmax_kernel(float* __restrict__ out)
{
    const int warp = (blockIdx.x * blockDim.x + threadIdx.x) >> 5;
    const int lane = threadIdx.x & 31;
    if (warp >= N_NODES) return;

    float* row = out + (size_t)warp * C_OUT;
    const float v0 = (lane < C_OUT) ? row[lane] : -__int_as_float(0x7f800000);
    const float v1 = (lane + 32 < C_OUT) ? row[lane + 32] : -__int_as_float(0x7f800000);

    float m = fmaxf(v0, v1);
    #pragma unroll
    for (int o = 16; o > 0; o >>= 1)
        m = fmaxf(m, __shfl_xor_sync(0xffffffffu, m, o));

    float s = ((lane < C_OUT) ? expf(v0 - m) : 0.f)
            + ((lane + 32 < C_OUT) ? expf(v1 - m) : 0.f);
    #pragma unroll
    for (int o = 16; o > 0; o >>= 1)
        s += __shfl_xor_sync(0xffffffffu, s, o);

    const float lse = m + logf(s);
    if (lane < C_OUT) row[lane] = v0 - lse;
    if (lane + 32 < C_OUT) row[lane + 32] = v1 - lse;
}

// ---------------------------------------------------------------------------
// Inputs: x, W1, b1, W2, b2, edge_row, edge_col, edge_val
// ---------------------------------------------------------------------------
extern "C" void kernel_launch(void* const* d_in, const int* in_sizes, int n_in,
                              void* d_out, int out_size)
{
    const float* x    = (const float*)d_in[0];
    const float* W1   = (const float*)d_in[1];
    const float* b1   = (const float*)d_in[2];
    const float* W2   = (const float*)d_in[3];
    const float* b2   = (const float*)d_in[4];
    const int*   erow = (const int*)d_in[5];
    const int*   ecol = (const int*)d_in[6];
    const float* eval = (const float*)d_in[7];
    float* out = (float*)d_out;

    const long long E = in_sizes[5];

    cudaFuncSetAttribute(fused_kernel,
                         cudaFuncAttributeMaxDynamicSharedMemorySize, DSMEM_BYTES);

    // prep weight images
    {
        const int total = HID * K_PAD + N2 * HID;
        prep_kernel<<<(total + 255) / 256, 256>>>(W1, b1, W2);
    }
    // fused GEMM1+GEMM2 -> g_h2, out = alpha*h2
    {
        const int blocks = (N_NODES + BM - 1) / BM;
        fused_kernel<<<blocks, 512, DSMEM_BYTES>>>(x, b2, out);
    }
    // edge scatter-add (10 threads/edge, vector red)
    {
        const long long total = E * 10;
        edge_kernel<<<(int)((total + 255) / 256), 256>>>(erow, ecol, eval, out, E);
    }
    // log_softmax
    {
        const long long threads = (long long)N_NODES * 32;
        logsoftmax_kernel<<<(int)((threads + 255) / 256), 256>>>(out);
    }
}